// round 4
// baseline (speedup 1.0000x reference)
#include <cuda_runtime.h>
#include <cstdint>

#define NN 100000
#define IN_CH 64
#define HID 64
#define N_CLS 40

// Scratch (allocation-free contract: __device__ globals).
// float4 type => 16-byte aligned base, required by red.global.add.v4.f32.
__device__ float4 g_Y4 [(size_t)NN * (HID / 4)];
__device__ float4 g_H14[(size_t)NN * (HID / 4)];
__device__ float4 g_Z4 [(size_t)NN * (HID / 4)];
__device__ int    g_deg[NN];

// ---------------------------------------------------------------------------
// Zero scratch: H1, Z (float4 granularity) and deg
// ---------------------------------------------------------------------------
__global__ void __launch_bounds__(256) zero_kernel(int n) {
    int t = blockIdx.x * blockDim.x + threadIdx.x;
    int nf4 = n * (HID / 4);
    float4 z4 = make_float4(0.f, 0.f, 0.f, 0.f);
    if (t < nf4) {
        g_H14[t] = z4;
    } else if (t < 2 * nf4) {
        g_Z4[t - nf4] = z4;
    }
    if (t < n) g_deg[t] = 0;
}

// ---------------------------------------------------------------------------
// Dense layer 1: Y = relu(NF @ W1 + b1), thread-per-row, W1 in smem
// ---------------------------------------------------------------------------
__global__ void __launch_bounds__(256) dense1_kernel(
    const float* __restrict__ nf, const float* __restrict__ W1,
    const float* __restrict__ b1, int n)
{
    __shared__ float Ws[IN_CH * HID];
    __shared__ float bs[HID];
    for (int i = threadIdx.x; i < IN_CH * HID; i += blockDim.x) Ws[i] = W1[i];
    for (int i = threadIdx.x; i < HID; i += blockDim.x) bs[i] = b1[i];
    __syncthreads();

    int row = blockIdx.x * blockDim.x + threadIdx.x;
    if (row >= n) return;

    float x[IN_CH];
    const float4* xr = reinterpret_cast<const float4*>(nf + (size_t)row * IN_CH);
    #pragma unroll
    for (int k4 = 0; k4 < IN_CH / 4; k4++) {
        float4 v = xr[k4];
        x[4*k4+0] = v.x; x[4*k4+1] = v.y; x[4*k4+2] = v.z; x[4*k4+3] = v.w;
    }

    float4* yr = g_Y4 + (size_t)row * (HID / 4);
    #pragma unroll 1
    for (int jj = 0; jj < HID / 4; jj++) {
        float4 acc = *reinterpret_cast<const float4*>(bs + jj * 4);
        #pragma unroll
        for (int k = 0; k < IN_CH; k++) {
            float4 w = *reinterpret_cast<const float4*>(Ws + k * HID + jj * 4);
            acc.x = fmaf(x[k], w.x, acc.x);
            acc.y = fmaf(x[k], w.y, acc.y);
            acc.z = fmaf(x[k], w.z, acc.z);
            acc.w = fmaf(x[k], w.w, acc.w);
        }
        acc.x = fmaxf(acc.x, 0.f); acc.y = fmaxf(acc.y, 0.f);
        acc.z = fmaxf(acc.z, 0.f); acc.w = fmaxf(acc.w, 0.f);
        yr[jj] = acc;
    }
}

// ---------------------------------------------------------------------------
// Sparse scatter-add pass: dst_tab[dst] += src_tab[src] per edge.
// 16 threads per edge, each moving one float4 via vector red.global.
// Edge index is INT32 (JAX x64 disabled -> int64 request yields int32).
// PASS==0: Y -> H1 (+ degree histogram);  PASS==1: H1 -> Z
// ---------------------------------------------------------------------------
template <int PASS>
__global__ void __launch_bounds__(256) scatter_kernel(
    const int* __restrict__ ei, int E)
{
    long long tid = (long long)blockIdx.x * blockDim.x + threadIdx.x;
    int e = (int)(tid >> 4);
    if (e >= E) return;
    int c = (int)(tid & 15);

    int s = __ldg(ei + e);
    int d = __ldg(ei + E + e);

    const float4* srct = (PASS == 0) ? g_Y4  : g_H14;
    float4*       dstt = (PASS == 0) ? g_H14 : g_Z4;

    float4 v = srct[(size_t)s * (HID / 4) + c];
    float4* p = dstt + (size_t)d * (HID / 4) + c;
    unsigned long long gp = (unsigned long long)__cvta_generic_to_global(p);
    asm volatile("red.global.add.v4.f32 [%0], {%1, %2, %3, %4};"
                 :: "l"(gp), "f"(v.x), "f"(v.y), "f"(v.z), "f"(v.w)
                 : "memory");

    if (PASS == 0 && c == 0) atomicAdd(&g_deg[d], 1);
}

// ---------------------------------------------------------------------------
// Fused dense tail: h2 = Z@W2 + deg*b2; logits = h2@Wf + bf; softmax -> out
// ---------------------------------------------------------------------------
__global__ void __launch_bounds__(128) dense2_kernel(
    const float* __restrict__ W2, const float* __restrict__ b2,
    const float* __restrict__ Wf, const float* __restrict__ bf,
    float* __restrict__ out, int n)
{
    __shared__ float W2s[HID * HID];
    __shared__ float Wfs[HID * N_CLS];
    __shared__ float b2s[HID];
    __shared__ float bfs[N_CLS];
    for (int i = threadIdx.x; i < HID * HID; i += blockDim.x) W2s[i] = W2[i];
    for (int i = threadIdx.x; i < HID * N_CLS; i += blockDim.x) Wfs[i] = Wf[i];
    for (int i = threadIdx.x; i < HID; i += blockDim.x) b2s[i] = b2[i];
    for (int i = threadIdx.x; i < N_CLS; i += blockDim.x) bfs[i] = bf[i];
    __syncthreads();

    int row = blockIdx.x * blockDim.x + threadIdx.x;
    if (row >= n) return;

    float z[HID];
    const float4* zr = g_Z4 + (size_t)row * (HID / 4);
    #pragma unroll
    for (int k4 = 0; k4 < HID / 4; k4++) {
        float4 v = zr[k4];
        z[4*k4+0] = v.x; z[4*k4+1] = v.y; z[4*k4+2] = v.z; z[4*k4+3] = v.w;
    }
    float degf = (float)g_deg[row];

    float logits[N_CLS];
    #pragma unroll
    for (int cc = 0; cc < N_CLS; cc++) logits[cc] = bfs[cc];

    #pragma unroll 1
    for (int jj = 0; jj < HID / 4; jj++) {
        float h[4];
        #pragma unroll
        for (int u = 0; u < 4; u++) h[u] = degf * b2s[jj * 4 + u];
        #pragma unroll
        for (int k = 0; k < HID; k++) {
            float4 w = *reinterpret_cast<const float4*>(W2s + k * HID + jj * 4);
            h[0] = fmaf(z[k], w.x, h[0]);
            h[1] = fmaf(z[k], w.y, h[1]);
            h[2] = fmaf(z[k], w.z, h[2]);
            h[3] = fmaf(z[k], w.w, h[3]);
        }
        #pragma unroll
        for (int u = 0; u < 4; u++) {
            int j = jj * 4 + u;
            #pragma unroll
            for (int c4 = 0; c4 < N_CLS / 4; c4++) {
                float4 w = *reinterpret_cast<const float4*>(Wfs + j * N_CLS + c4 * 4);
                logits[c4*4+0] = fmaf(h[u], w.x, logits[c4*4+0]);
                logits[c4*4+1] = fmaf(h[u], w.y, logits[c4*4+1]);
                logits[c4*4+2] = fmaf(h[u], w.z, logits[c4*4+2]);
                logits[c4*4+3] = fmaf(h[u], w.w, logits[c4*4+3]);
            }
        }
    }

    // softmax over N_CLS
    float m = logits[0];
    #pragma unroll
    for (int cc = 1; cc < N_CLS; cc++) m = fmaxf(m, logits[cc]);
    float ssum = 0.f;
    #pragma unroll
    for (int cc = 0; cc < N_CLS; cc++) {
        float ev = __expf(logits[cc] - m);
        logits[cc] = ev;
        ssum += ev;
    }
    float inv = 1.f / ssum;
    float* orow = out + (size_t)row * N_CLS;
    #pragma unroll
    for (int c4 = 0; c4 < N_CLS / 4; c4++) {
        float4 o;
        o.x = logits[c4*4+0] * inv; o.y = logits[c4*4+1] * inv;
        o.z = logits[c4*4+2] * inv; o.w = logits[c4*4+3] * inv;
        *reinterpret_cast<float4*>(orow + c4 * 4) = o;
    }
}

// ---------------------------------------------------------------------------
extern "C" void kernel_launch(void* const* d_in, const int* in_sizes, int n_in,
                              void* d_out, int out_size)
{
    const float* nf = (const float*)d_in[0];
    const int*   ei = (const int*)d_in[1];   // int32! (JAX x64 disabled)
    const float* W1 = (const float*)d_in[2];
    const float* b1 = (const float*)d_in[3];
    const float* W2 = (const float*)d_in[4];
    const float* b2 = (const float*)d_in[5];
    const float* Wf = (const float*)d_in[6];
    const float* bf = (const float*)d_in[7];
    float* out = (float*)d_out;

    int n = in_sizes[0] / IN_CH;   // 100000
    int E = in_sizes[1] / 2;       // 1600000

    int nf4 = n * (HID / 4);
    zero_kernel<<<(2 * nf4 + 255) / 256, 256>>>(n);
    dense1_kernel<<<(n + 255) / 256, 256>>>(nf, W1, b1, n);

    long long work = (long long)E * 16;
    int sblocks = (int)((work + 255) / 256);
    scatter_kernel<0><<<sblocks, 256>>>(ei, E);
    scatter_kernel<1><<<sblocks, 256>>>(ei, E);

    dense2_kernel<<<(n + 127) / 128, 128>>>(W2, b2, Wf, bf, out, n);
}